// round 15
// baseline (speedup 1.0000x reference)
#include <cuda_runtime.h>
#include <cuda_fp16.h>
#include <math.h>
#include <stdint.h>

#define EDIM 1024
#define TSEQ 2048
#define NTOK 4096
#define FFD  4096
#define LN_EPS 1e-5f
#define MEGA 1048576
#define QSCALE 0.18033688f   /* 0.125 * log2(e) */

__device__ __half g_wh  [(size_t)16*MEGA];
__device__ __half g_ench[(size_t)NTOK*EDIM];
__device__ __half g_hh  [(size_t)NTOK*EDIM];
__device__ __half g_qkvh[(size_t)12*MEGA];
__device__ __half g_qh  [(size_t)NTOK*EDIM];
__device__ __half g_aoh [(size_t)NTOK*EDIM];
__device__ __half g_ffh [(size_t)NTOK*FFD];
__device__ float  g_x1  [(size_t)NTOK*EDIM];
__device__ float  g_x2  [(size_t)NTOK*EDIM];
__device__ float  g_bqkv[3072];
__device__ float  g_bkv [2048];
__device__ float  g_bqc [1024];

// ---------------- primitives ----------------
__device__ __forceinline__ void mma_f16(float* c, const uint32_t* a, uint32_t b0, uint32_t b1){
    asm volatile("mma.sync.aligned.m16n8k16.row.col.f32.f16.f16.f32 "
        "{%0,%1,%2,%3}, {%4,%5,%6,%7}, {%8,%9}, {%0,%1,%2,%3};"
        : "+f"(c[0]), "+f"(c[1]), "+f"(c[2]), "+f"(c[3])
        : "r"(a[0]), "r"(a[1]), "r"(a[2]), "r"(a[3]), "r"(b0), "r"(b1));
}
__device__ __forceinline__ void ldsm4(uint32_t* r, uint32_t a){
    asm volatile("ldmatrix.sync.aligned.m8n8.x4.shared.b16 {%0,%1,%2,%3}, [%4];"
        : "=r"(r[0]), "=r"(r[1]), "=r"(r[2]), "=r"(r[3]) : "r"(a));
}
__device__ __forceinline__ void ldsm4t(uint32_t* r, uint32_t a){
    asm volatile("ldmatrix.sync.aligned.m8n8.x4.trans.shared.b16 {%0,%1,%2,%3}, [%4];"
        : "=r"(r[0]), "=r"(r[1]), "=r"(r[2]), "=r"(r[3]) : "r"(a));
}
__device__ __forceinline__ void cpa16(uint32_t dst, const void* src){
    asm volatile("cp.async.cg.shared.global [%0], [%1], 16;" :: "r"(dst), "l"(src));
}
#define CP_COMMIT() asm volatile("cp.async.commit_group;")
#define CP_WAIT(n)  asm volatile("cp.async.wait_group %0;" :: "n"(n))
__device__ __forceinline__ uint32_t pack2(float lo, float hi){
    __half2 h = __floats2half2_rn(lo, hi);
    return *(uint32_t*)&h;
}
__device__ __forceinline__ uint32_t pexp2(float lo, float hi){
    __half2 h = h2exp2(__floats2half2_rn(lo, hi));
    return *(uint32_t*)&h;
}
#define HONES 0x3C003C00u

// ---------------- mega convert (Q weights/biases pre-scaled by QSCALE) -------
#define SEGP 262144
__global__ __launch_bounds__(256)
void cvt_all(const float* __restrict__ sa_wq, const float* __restrict__ sa_wk,
             const float* __restrict__ sa_wv, const float* __restrict__ sa_wo,
             const float* __restrict__ ca_wq, const float* __restrict__ ca_wk,
             const float* __restrict__ ca_wv, const float* __restrict__ ca_wo,
             const float* __restrict__ ff_w1, const float* __restrict__ ff_w2,
             const float* __restrict__ enc,
             const float* __restrict__ sa_bq, const float* __restrict__ sa_bk,
             const float* __restrict__ sa_bv,
             const float* __restrict__ ca_bq,
             const float* __restrict__ ca_bk, const float* __restrict__ ca_bv,
             __half* __restrict__ wh, __half* __restrict__ ench,
             float* __restrict__ bqkv, float* __restrict__ bkv,
             float* __restrict__ bqc)
{
    const long i = (long)blockIdx.x*256 + threadIdx.x;
    if (i < 8L*SEGP){
        const int seg = (int)(i / SEGP);
        const int li  = (int)(i % SEGP);
        float4 v = ((const float4*)(seg==0?sa_wq: seg==1?sa_wk: seg==2?sa_wv:
                     seg==3?sa_wo: seg==4?ca_wq: seg==5?ca_wk: seg==6?ca_wv:ca_wo))[li];
        if (seg == 0 || seg == 4){
            v.x *= QSCALE; v.y *= QSCALE; v.z *= QSCALE; v.w *= QSCALE;
        }
        uint2 o; o.x = pack2(v.x, v.y); o.y = pack2(v.z, v.w);
        size_t d;
        const int row = li >> 8, n = (li & 255) * 4;
        if (seg <= 2)       d = (size_t)row*3072 + seg*1024 + n;
        else if (seg == 3)  d = (size_t)3*MEGA + (size_t)li*4;
        else if (seg == 4)  d = (size_t)4*MEGA + (size_t)li*4;
        else if (seg <= 6)  d = (size_t)5*MEGA + (size_t)row*2048 + (seg-5)*1024 + n;
        else                d = (size_t)7*MEGA + (size_t)li*4;
        *(uint2*)&wh[d] = o;
        return;
    }
    long j = i - 8L*SEGP;
    if (j < (long)MEGA){
        const float4 v = ((const float4*)ff_w1)[j];
        uint2 o; o.x = pack2(v.x,v.y); o.y = pack2(v.z,v.w);
        *(uint2*)&wh[(size_t)8*MEGA + (size_t)j*4] = o;
        return;
    }
    j -= MEGA;
    if (j < (long)MEGA){
        const float4 v = ((const float4*)ff_w2)[j];
        uint2 o; o.x = pack2(v.x,v.y); o.y = pack2(v.z,v.w);
        *(uint2*)&wh[(size_t)12*MEGA + (size_t)j*4] = o;
        return;
    }
    j -= MEGA;
    if (j < (long)MEGA){
        const float4 v = ((const float4*)enc)[j];
        uint2 o; o.x = pack2(v.x,v.y); o.y = pack2(v.z,v.w);
        *(uint2*)&ench[(size_t)j*4] = o;
        return;
    }
    j -= MEGA;
    if (j < 768){
        const int e = (int)j * 4;
        const int sub = e >> 10, idx = e & 1023;
        float4 v = *(const float4*)&((sub==0?sa_bq: sub==1?sa_bk:sa_bv)[idx]);
        if (sub == 0){ v.x*=QSCALE; v.y*=QSCALE; v.z*=QSCALE; v.w*=QSCALE; }
        *(float4*)&bqkv[e] = v;
        return;
    }
    j -= 768;
    if (j < 512){
        const int e = (int)j * 4;
        const int sub = e >> 10, idx = e & 1023;
        *(float4*)&bkv[e] = *(const float4*)&((sub==0?ca_bk:ca_bv)[idx]);
        return;
    }
    j -= 512;
    if (j < 256){
        const int e = (int)j * 4;
        float4 v = *(const float4*)&ca_bq[e];
        v.x*=QSCALE; v.y*=QSCALE; v.z*=QSCALE; v.w*=QSCALE;
        *(float4*)&bqc[e] = v;
    }
}

// ---------------- LayerNorm (fp32 in, half out) ----------------
__global__ __launch_bounds__(256)
void ln_kernel(const float* __restrict__ x, const float* __restrict__ gamma,
               const float* __restrict__ beta, __half* __restrict__ out)
{
    const int row = blockIdx.x;
    const int t = threadIdx.x;
    const float4 v = ((const float4*)(x + (size_t)row*EDIM))[t];
    float s  = v.x + v.y + v.z + v.w;
    float ss = v.x*v.x + v.y*v.y + v.z*v.z + v.w*v.w;
#pragma unroll
    for (int o = 16; o; o >>= 1){
        s  += __shfl_xor_sync(0xffffffffu, s,  o);
        ss += __shfl_xor_sync(0xffffffffu, ss, o);
    }
    __shared__ float sh_s[8], sh_ss[8];
    const int w = t >> 5, l = t & 31;
    if (l == 0){ sh_s[w] = s; sh_ss[w] = ss; }
    __syncthreads();
    if (w == 0){
        s  = (l < 8) ? sh_s[l]  : 0.f;
        ss = (l < 8) ? sh_ss[l] : 0.f;
#pragma unroll
        for (int o = 4; o; o >>= 1){
            s  += __shfl_xor_sync(0xffffffffu, s,  o);
            ss += __shfl_xor_sync(0xffffffffu, ss, o);
        }
        if (l == 0){ sh_s[0] = s; sh_ss[0] = ss; }
    }
    __syncthreads();
    const float mu   = sh_s[0] * (1.f/EDIM);
    const float var  = sh_ss[0] * (1.f/EDIM) - mu*mu;
    const float rstd = rsqrtf(var + LN_EPS);
    const float4 g4 = ((const float4*)gamma)[t];
    const float4 b4 = ((const float4*)beta)[t];
    __half2* orow = (__half2*)(out + (size_t)row*EDIM);
    orow[2*t]   = __floats2half2_rn((v.x-mu)*rstd*g4.x + b4.x, (v.y-mu)*rstd*g4.y + b4.y);
    orow[2*t+1] = __floats2half2_rn((v.z-mu)*rstd*g4.z + b4.z, (v.w-mu)*rstd*g4.w + b4.w);
}

// ---------------- FP16 GEMM body, BK=64, 3-stage cp.async, A-frag pipelined --
#define ASTG 9216
#define BSTG 8704
#define GEMM_SMEM ((3*(ASTG + BSTG))*2)
template<bool RELU, bool RES, bool OUTH>
__device__ __forceinline__
void gemm_body(const __half* __restrict__ A, const __half* __restrict__ W,
               const float* __restrict__ bias, const float* __restrict__ res,
               void* __restrict__ Cv, int N, int K, int m0, int n0)
{
    extern __shared__ __half gsm[];
    __half* As = gsm;
    __half* Bs = gsm + 3*ASTG;

    const int tid  = threadIdx.x;
    const int lane = tid & 31;
    const int wid  = tid >> 5;
    const int gid  = lane >> 2;
    const int tig  = lane & 3;
    const int wm   = (wid & 3) * 32;
    const int wn   = (wid >> 2) * 64;

    const uint32_t asb = (uint32_t)__cvta_generic_to_shared(As);
    const uint32_t bsb = (uint32_t)__cvta_generic_to_shared(Bs);

    const int a_r = wm + (lane&7) + ((lane>>3)&1)*8;
    const int a_k = ((lane>>4)&1)*8;
    const int b_k = (lane&7) + ((lane>>3)&1)*8;
    const int b_n = wn + ((lane>>4)&1)*8;

    float acc[2][8][4];
#pragma unroll
    for (int i=0;i<2;i++)
#pragma unroll
        for (int j=0;j<8;j++)
#pragma unroll
            for (int k=0;k<4;k++) acc[i][j][k]=0.f;

#define LOADSTAGE(b_, kt_) do{                                               \
        _Pragma("unroll")                                                    \
        for (int i=0;i<4;i++){                                               \
            int idx = tid + 256*i;                                           \
            int ar = idx>>3, ac = (idx&7)*8;                                 \
            cpa16(asb + (uint32_t)(((b_)*ASTG + ar*72 + ac)*2),              \
                  A + (size_t)(m0+ar)*K + (kt_)*64 + ac);                    \
        }                                                                    \
        _Pragma("unroll")                                                    \
        for (int i=0;i<4;i++){                                               \
            int idx = tid + 256*i;                                           \
            int kr = idx>>4, nc = (idx&15)*8;                                \
            cpa16(bsb + (uint32_t)(((b_)*BSTG + kr*136 + nc)*2),             \
                  W + (size_t)((kt_)*64+kr)*N + n0 + nc);                    \
        }                                                                    \
        CP_COMMIT();                                                         \
    }while(0)

    LOADSTAGE(0, 0);
    LOADSTAGE(1, 1);
    const int KT = K >> 6;
    for (int kt = 0; kt < KT; ++kt){
        CP_WAIT(1);
        __syncthreads();
        if (kt + 2 < KT) LOADSTAGE((kt+2)%3, kt+2);
        else CP_COMMIT();
        const int buf = kt % 3;
        const uint32_t asb_b = asb + (uint32_t)(buf*ASTG*2);
        const uint32_t bsb_b = bsb + (uint32_t)(buf*BSTG*2);
        // A-fragment pipeline: load kc=0, then prefetch kc+1 while mma(kc) runs
        uint32_t af[2][4];
#pragma unroll
        for (int ma = 0; ma < 2; ma++)
            ldsm4(af[ma], asb_b + (uint32_t)(((a_r + ma*16)*72 + a_k)*2));
#pragma unroll
        for (int kc = 0; kc < 4; kc++){
            uint32_t afn[2][4];
            if (kc < 3){
#pragma unroll
                for (int ma = 0; ma < 2; ma++)
                    ldsm4(afn[ma], asb_b + (uint32_t)(((a_r + ma*16)*72 + a_k + (kc+1)*16)*2));
            }
#pragma unroll
            for (int np = 0; np < 4; np++){
                uint32_t bf[4];
                ldsm4t(bf, bsb_b + (uint32_t)(((b_k + kc*16)*136 + b_n + np*16)*2));
                mma_f16(acc[0][2*np  ], af[0], bf[0], bf[1]);
                mma_f16(acc[0][2*np+1], af[0], bf[2], bf[3]);
                mma_f16(acc[1][2*np  ], af[1], bf[0], bf[1]);
                mma_f16(acc[1][2*np+1], af[1], bf[2], bf[3]);
            }
            if (kc < 3){
#pragma unroll
                for (int ma = 0; ma < 2; ma++)
#pragma unroll
                    for (int e = 0; e < 4; e++) af[ma][e] = afn[ma][e];
            }
        }
    }
#undef LOADSTAGE

#pragma unroll
    for (int ma = 0; ma < 2; ma++){
        const int r0 = m0 + wm + ma*16 + gid;
        const int r1 = r0 + 8;
#pragma unroll
        for (int na = 0; na < 8; na++){
            const int c = n0 + wn + na*8 + 2*tig;
            const float2 bb = *(const float2*)&bias[c];
            float v00 = acc[ma][na][0] + bb.x;
            float v01 = acc[ma][na][1] + bb.y;
            float v10 = acc[ma][na][2] + bb.x;
            float v11 = acc[ma][na][3] + bb.y;
            if (RELU){
                v00 = fmaxf(v00,0.f); v01 = fmaxf(v01,0.f);
                v10 = fmaxf(v10,0.f); v11 = fmaxf(v11,0.f);
            }
            if (RES){
                const float2 q0 = *(const float2*)&res[(size_t)r0*N + c];
                const float2 q1 = *(const float2*)&res[(size_t)r1*N + c];
                v00 += q0.x; v01 += q0.y; v10 += q1.x; v11 += q1.y;
            }
            if (OUTH){
                __half* Ch = (__half*)Cv;
                *(__half2*)&Ch[(size_t)r0*N + c] = __floats2half2_rn(v00, v01);
                *(__half2*)&Ch[(size_t)r1*N + c] = __floats2half2_rn(v10, v11);
            } else {
                float* Cf = (float*)Cv;
                float2 o0; o0.x=v00; o0.y=v01;
                float2 o1; o1.x=v10; o1.y=v11;
                *(float2*)&Cf[(size_t)r0*N + c] = o0;
                *(float2*)&Cf[(size_t)r1*N + c] = o1;
            }
        }
    }
}

template<bool RELU, bool RES, bool OUTH>
__global__ __launch_bounds__(256,2)
void gemm_h(const __half* __restrict__ A, const __half* __restrict__ W,
            const float* __restrict__ bias, const float* __restrict__ res,
            void* __restrict__ Cv, int N, int K)
{
    gemm_body<RELU,RES,OUTH>(A, W, bias, res, Cv, N, K,
                             blockIdx.y*128, blockIdx.x*128);
}

__global__ __launch_bounds__(256,2)
void gemm_dual(const __half* __restrict__ A0, const __half* __restrict__ W0,
               const float* __restrict__ b0, __half* __restrict__ C0,
               const __half* __restrict__ A1, const __half* __restrict__ W1,
               const float* __restrict__ b1, __half* __restrict__ C1)
{
    const int bx = blockIdx.x;
    const __half* A; const __half* W; const float* bias; __half* C; int N, n0;
    if (bx < 8){ A = A0; W = W0; bias = b0; C = C0; N = 1024; n0 = bx*128; }
    else       { A = A1; W = W1; bias = b1; C = C1; N = 2048; n0 = (bx-8)*128; }
    gemm_body<false,false,true>(A, W, bias, nullptr, C, N, 1024,
                                blockIdx.y*128, n0);
}

// ---------------- Flash attention fp16 (R13 proven loop) ----------------
#define ATP 72
#define KVB (64*ATP)
#define ATTN_SMEM ((128*ATP + 4*KVB)*2)
template<bool CAUSAL>
__global__ __launch_bounds__(256,2)
void attn_h(const __half* __restrict__ Qg, const __half* __restrict__ Kg,
            const __half* __restrict__ Vg, __half* __restrict__ Og,
            int ldq, int ldkv)
{
    extern __shared__ __half smh[];
    __half* Qs = smh;
    __half* Ks = Qs + 128*ATP;
    __half* Vs = Ks + 2*KVB;

    const int tid  = threadIdx.x;
    const int lane = tid & 31;
    const int wid  = tid >> 5;
    const int gid  = lane >> 2;
    const int tig  = lane & 3;
    const int wm   = wid * 16;
    const int qb = CAUSAL ? ((int)gridDim.x - 1 - (int)blockIdx.x) : (int)blockIdx.x;
    const int h = blockIdx.y, b = blockIdx.z;
    const size_t baseq = (size_t)b*TSEQ*ldq  + (size_t)h*64;
    const size_t basek = (size_t)b*TSEQ*ldkv + (size_t)h*64;
    const size_t baseo = (size_t)b*TSEQ*EDIM + (size_t)h*64;

    const uint32_t qsb = (uint32_t)__cvta_generic_to_shared(Qs);
    const uint32_t ksb = (uint32_t)__cvta_generic_to_shared(Ks);
    const uint32_t vsb = (uint32_t)__cvta_generic_to_shared(Vs);

#pragma unroll
    for (int i = 0; i < 4; i++){
        int idx = tid + 256*i;
        int r = idx>>3, c = (idx&7)*8;
        cpa16(qsb + (uint32_t)((r*ATP + c)*2), Qg + baseq + (size_t)(qb*128 + r)*ldq + c);
    }
    CP_COMMIT();
#define LOADKV(b_, kt_) do{                                                   \
        _Pragma("unroll")                                                     \
        for (int i = 0; i < 2; i++){                                          \
            int idx = tid + 256*i;                                            \
            int r = idx>>3, c = (idx&7)*8;                                    \
            size_t go = basek + (size_t)((kt_)*64 + r)*ldkv + c;              \
            uint32_t so = (uint32_t)(((b_)*KVB + r*ATP + c)*2);               \
            cpa16(ksb + so, Kg + go);                                         \
            cpa16(vsb + so, Vg + go);                                         \
        }                                                                     \
        CP_COMMIT();                                                          \
    }while(0)
    LOADKV(0, 0);
    CP_WAIT(1);
    __syncthreads();

    const int q_r = wm + (lane&7) + ((lane>>3)&1)*8;
    const int q_k = ((lane>>4)&1)*8;
    uint32_t qf[4][4];
#pragma unroll
    for (int kc = 0; kc < 4; kc++)
        ldsm4(qf[kc], qsb + (uint32_t)((q_r*ATP + q_k + kc*16)*2));

    const int k_r = (lane&7);
    const int k_c = (lane>>3)*8;
    const int v_r = (lane&7) + ((lane>>3)&1)*8;
    const int v_n = ((lane>>4)&1)*8;

    float oacc[8][4];
#pragma unroll
    for (int i=0;i<8;i++)
#pragma unroll
        for (int j=0;j<4;j++) oacc[i][j]=0.f;
    float m0=-1e30f, m1=-1e30f, l0=0.f, l1=0.f;

    const int nkt = CAUSAL ? (2*qb + 2) : (TSEQ/64);
    const int gr0 = qb*128 + wm + gid;
    const int gr1 = gr0 + 8;

    for (int kt = 0; kt < nkt; ++kt){
        CP_WAIT(0);
        __syncthreads();
        const int buf = kt & 1;
        if (kt + 1 < nkt) LOADKV(buf^1, kt+1);
        const uint32_t ksb_b = ksb + (uint32_t)(buf*KVB*2);
        const uint32_t vsb_b = vsb + (uint32_t)(buf*KVB*2);

        float sa[8][4];
#pragma unroll
        for (int na=0;na<8;na++)
#pragma unroll
            for (int e=0;e<4;e++) sa[na][e]=0.f;
#pragma unroll
        for (int na = 0; na < 8; na++){
#pragma unroll
            for (int kq = 0; kq < 2; kq++){
                uint32_t kf[4];
                ldsm4(kf, ksb_b + (uint32_t)(((na*8 + k_r)*ATP + kq*32 + k_c)*2));
                mma_f16(sa[na], qf[2*kq  ], kf[0], kf[1]);
                mma_f16(sa[na], qf[2*kq+1], kf[2], kf[3]);
            }
        }
        if (CAUSAL && kt >= 2*qb){
#pragma unroll
            for (int na = 0; na < 8; na++){
                const int c0 = kt*64 + na*8 + 2*tig;
#pragma unroll
                for (int e = 0; e < 4; e++){
                    const int col = c0 + (e&1);
                    const int row = (e<2) ? gr0 : gr1;
                    if (col > row) sa[na][e] = -1e30f;
                }
            }
        }
        float mx0=-1e30f, mx1=-1e30f;
#pragma unroll
        for (int na=0;na<8;na++){
            mx0 = fmaxf(mx0, fmaxf(sa[na][0], sa[na][1]));
            mx1 = fmaxf(mx1, fmaxf(sa[na][2], sa[na][3]));
        }
        mx0 = fmaxf(mx0, __shfl_xor_sync(0xffffffffu, mx0, 1));
        mx0 = fmaxf(mx0, __shfl_xor_sync(0xffffffffu, mx0, 2));
        mx1 = fmaxf(mx1, __shfl_xor_sync(0xffffffffu, mx1, 1));
        mx1 = fmaxf(mx1, __shfl_xor_sync(0xffffffffu, mx1, 2));
        const float mn0 = fmaxf(m0, mx0);
        const float mn1 = fmaxf(m1, mx1);
        const float al0 = exp2f(m0 - mn0);
        const float al1 = exp2f(m1 - mn1);
        m0 = mn0; m1 = mn1;
        uint32_t pf[4][4];
#pragma unroll
        for (int kc = 0; kc < 4; kc++){
            pf[kc][0] = pexp2(sa[2*kc  ][0]-mn0, sa[2*kc  ][1]-mn0);
            pf[kc][1] = pexp2(sa[2*kc  ][2]-mn1, sa[2*kc  ][3]-mn1);
            pf[kc][2] = pexp2(sa[2*kc+1][0]-mn0, sa[2*kc+1][1]-mn0);
            pf[kc][3] = pexp2(sa[2*kc+1][2]-mn1, sa[2*kc+1][3]-mn1);
        }
        float lacc[4] = {0.f, 0.f, 0.f, 0.f};
#pragma unroll
        for (int kc = 0; kc < 4; kc++)
            mma_f16(lacc, pf[kc], HONES, HONES);
        l0 = l0*al0 + lacc[0];
        l1 = l1*al1 + lacc[2];
#pragma unroll
        for (int na=0;na<8;na++){
            oacc[na][0]*=al0; oacc[na][1]*=al0;
            oacc[na][2]*=al1; oacc[na][3]*=al1;
        }
#pragma unroll
        for (int kc = 0; kc < 4; kc++){
#pragma unroll
            for (int np = 0; np < 4; np++){
                uint32_t vf[4];
                ldsm4t(vf, vsb_b + (uint32_t)(((kc*16 + v_r)*ATP + v_n + np*16)*2));
                mma_f16(oacc[2*np  ], pf[kc], vf[0], vf[1]);
                mma_f16(oacc[2*np+1], pf[kc], vf[2], vf[3]);
            }
        }
    }
#undef LOADKV

    const float li0 = 1.f / l0;
    const float li1 = 1.f / l1;
#pragma unroll
    for (int na = 0; na < 8; na++){
        const int c = na*8 + 2*tig;
        *(__half2*)&Og[baseo + (size_t)gr0*EDIM + c] =
            __floats2half2_rn(oacc[na][0]*li0, oacc[na][1]*li0);
        *(__half2*)&Og[baseo + (size_t)gr1*EDIM + c] =
            __floats2half2_rn(oacc[na][2]*li1, oacc[na][3]*li1);
    }
}

// ---------------- launch ----------------
extern "C" void kernel_launch(void* const* d_in, const int* in_sizes, int n_in,
                              void* d_out, int out_size)
{
    const float* x     = (const float*)d_in[0];
    const float* enc   = (const float*)d_in[1];
    const float* sa_wq = (const float*)d_in[3];  const float* sa_bq = (const float*)d_in[4];
    const float* sa_wk = (const float*)d_in[5];  const float* sa_bk = (const float*)d_in[6];
    const float* sa_wv = (const float*)d_in[7];  const float* sa_bv = (const float*)d_in[8];
    const float* sa_wo = (const float*)d_in[9];  const float* sa_bo = (const float*)d_in[10];
    const float* ca_wq = (const float*)d_in[11]; const float* ca_bq = (const float*)d_in[12];
    const float* ca_wk = (const float*)d_in[13]; const float* ca_bk = (const float*)d_in[14];
    const float* ca_wv = (const float*)d_in[15]; const float* ca_bv = (const float*)d_in[16];
    const float* ca_wo = (const float*)d_in[17]; const float* ca_bo = (const float*)d_in[18];
    const float* ff_w1 = (const float*)d_in[19]; const float* ff_b1 = (const float*)d_in[20];
    const float* ff_w2 = (const float*)d_in[21]; const float* ff_b2 = (const float*)d_in[22];
    const float* ln1g  = (const float*)d_in[23]; const float* ln1b  = (const float*)d_in[24];
    const float* ln2g  = (const float*)d_in[25]; const float* ln2b  = (const float*)d_in[26];
    const float* ln3g  = (const float*)d_in[27]; const float* ln3b  = (const float*)d_in[28];
    float* out = (float*)d_out;

    __half *wh, *ench, *hh, *qkvh, *qh, *aoh, *ffh;
    float *x1, *x2, *bqkv, *bkv, *bqc;
    cudaGetSymbolAddress((void**)&wh,   g_wh);
    cudaGetSymbolAddress((void**)&ench, g_ench);
    cudaGetSymbolAddress((void**)&hh,   g_hh);
    cudaGetSymbolAddress((void**)&qkvh, g_qkvh);
    cudaGetSymbolAddress((void**)&qh,   g_qh);
    cudaGetSymbolAddress((void**)&aoh,  g_aoh);
    cudaGetSymbolAddress((void**)&ffh,  g_ffh);
    cudaGetSymbolAddress((void**)&x1,   g_x1);
    cudaGetSymbolAddress((void**)&x2,   g_x2);
    cudaGetSymbolAddress((void**)&bqkv, g_bqkv);
    cudaGetSymbolAddress((void**)&bkv,  g_bkv);
    cudaGetSymbolAddress((void**)&bqc,  g_bqc);

    cudaFuncSetAttribute(attn_h<true>,  cudaFuncAttributeMaxDynamicSharedMemorySize, ATTN_SMEM);
    cudaFuncSetAttribute(attn_h<false>, cudaFuncAttributeMaxDynamicSharedMemorySize, ATTN_SMEM);
    cudaFuncSetAttribute(gemm_h<false,false,true >, cudaFuncAttributeMaxDynamicSharedMemorySize, GEMM_SMEM);
    cudaFuncSetAttribute(gemm_h<false,true ,false>, cudaFuncAttributeMaxDynamicSharedMemorySize, GEMM_SMEM);
    cudaFuncSetAttribute(gemm_h<true ,false,true >, cudaFuncAttributeMaxDynamicSharedMemorySize, GEMM_SMEM);
    cudaFuncSetAttribute(gemm_dual, cudaFuncAttributeMaxDynamicSharedMemorySize, GEMM_SMEM);

    const long cvt_total = 8L*SEGP + 3L*MEGA + 1536;
    cvt_all<<<(unsigned)((cvt_total + 255)/256), 256>>>(
        sa_wq, sa_wk, sa_wv, sa_wo, ca_wq, ca_wk, ca_wv, ca_wo,
        ff_w1, ff_w2, enc, sa_bq, sa_bk, sa_bv, ca_bq, ca_bk, ca_bv,
        wh, ench, bqkv, bkv, bqc);

    const dim3 thr(256);
    const dim3 gQKV(3072/128, NTOK/128);
    const dim3 gP  (EDIM/128, NTOK/128);
    const dim3 gF1 (FFD/128,  NTOK/128);
    const dim3 gD  (24, NTOK/128);
    const dim3 gA  (TSEQ/128, 16, 2);

    // ---- self attention ----
    ln_kernel<<<NTOK, 256>>>(x, ln1g, ln1b, hh);
    gemm_h<false,false,true ><<<gQKV, thr, GEMM_SMEM>>>(hh, wh, bqkv, nullptr, qkvh, 3072, 1024);
    attn_h<true><<<gA, thr, ATTN_SMEM>>>(qkvh, qkvh+1024, qkvh+2048, aoh, 3072, 3072);
    gemm_h<false,true ,false><<<gP, thr, GEMM_SMEM>>>(aoh, wh+(size_t)3*MEGA, sa_bo, x, x1, EDIM, EDIM);

    // ---- cross attention (Q proj + KV proj fused) ----
    ln_kernel<<<NTOK, 256>>>(x1, ln2g, ln2b, hh);
    gemm_dual<<<gD, thr, GEMM_SMEM>>>(hh, wh+(size_t)4*MEGA, bqc, qh,
                                      ench, wh+(size_t)5*MEGA, bkv, qkvh);
    attn_h<false><<<gA, thr, ATTN_SMEM>>>(qh, qkvh, qkvh+1024, aoh, 1024, 2048);
    gemm_h<false,true ,false><<<gP, thr, GEMM_SMEM>>>(aoh, wh+(size_t)7*MEGA, ca_bo, x1, x2, EDIM, EDIM);

    // ---- feed-forward ----
    ln_kernel<<<NTOK, 256>>>(x2, ln3g, ln3b, hh);
    gemm_h<true ,false,true ><<<gF1, thr, GEMM_SMEM>>>(hh,  wh+(size_t)8*MEGA,  ff_b1, nullptr, ffh, FFD, 1024);
    gemm_h<false,true ,false><<<gP, thr, GEMM_SMEM>>>(ffh, wh+(size_t)12*MEGA, ff_b2, x2, out, EDIM, FFD);
}

// round 16
// speedup vs baseline: 1.0331x; 1.0331x over previous
#include <cuda_runtime.h>
#include <cuda_fp16.h>
#include <math.h>
#include <stdint.h>

#define EDIM 1024
#define TSEQ 2048
#define NTOK 4096
#define FFD  4096
#define LN_EPS 1e-5f
#define MEGA 1048576
#define QSCALE 0.18033688f   /* 0.125 * log2(e) */

__device__ __half g_wh  [(size_t)16*MEGA];
__device__ __half g_ench[(size_t)NTOK*EDIM];
__device__ __half g_hh  [(size_t)NTOK*EDIM];
__device__ __half g_qkvh[(size_t)12*MEGA];
__device__ __half g_kvc [(size_t)8*MEGA];
__device__ __half g_qh  [(size_t)NTOK*EDIM];
__device__ __half g_aoh [(size_t)NTOK*EDIM];
__device__ __half g_ffh [(size_t)NTOK*FFD];
__device__ float  g_x1  [(size_t)NTOK*EDIM];
__device__ float  g_x2  [(size_t)NTOK*EDIM];
__device__ float  g_bqkv[3072];
__device__ float  g_bkv [2048];
__device__ float  g_bqc [1024];

// ---------------- primitives ----------------
__device__ __forceinline__ void mma_f16(float* c, const uint32_t* a, uint32_t b0, uint32_t b1){
    asm volatile("mma.sync.aligned.m16n8k16.row.col.f32.f16.f16.f32 "
        "{%0,%1,%2,%3}, {%4,%5,%6,%7}, {%8,%9}, {%0,%1,%2,%3};"
        : "+f"(c[0]), "+f"(c[1]), "+f"(c[2]), "+f"(c[3])
        : "r"(a[0]), "r"(a[1]), "r"(a[2]), "r"(a[3]), "r"(b0), "r"(b1));
}
__device__ __forceinline__ void ldsm4(uint32_t* r, uint32_t a){
    asm volatile("ldmatrix.sync.aligned.m8n8.x4.shared.b16 {%0,%1,%2,%3}, [%4];"
        : "=r"(r[0]), "=r"(r[1]), "=r"(r[2]), "=r"(r[3]) : "r"(a));
}
__device__ __forceinline__ void ldsm4t(uint32_t* r, uint32_t a){
    asm volatile("ldmatrix.sync.aligned.m8n8.x4.trans.shared.b16 {%0,%1,%2,%3}, [%4];"
        : "=r"(r[0]), "=r"(r[1]), "=r"(r[2]), "=r"(r[3]) : "r"(a));
}
__device__ __forceinline__ void cpa16(uint32_t dst, const void* src){
    asm volatile("cp.async.cg.shared.global [%0], [%1], 16;" :: "r"(dst), "l"(src));
}
#define CP_COMMIT() asm volatile("cp.async.commit_group;")
#define CP_WAIT(n)  asm volatile("cp.async.wait_group %0;" :: "n"(n))
__device__ __forceinline__ uint32_t pack2(float lo, float hi){
    __half2 h = __floats2half2_rn(lo, hi);
    return *(uint32_t*)&h;
}
__device__ __forceinline__ uint32_t pexp2(float lo, float hi){
    __half2 h = h2exp2(__floats2half2_rn(lo, hi));
    return *(uint32_t*)&h;
}
#define HONES 0x3C003C00u

// ---------------- mega convert (Q weights/biases pre-scaled by QSCALE) -------
#define SEGP 262144
__global__ __launch_bounds__(256)
void cvt_all(const float* __restrict__ sa_wq, const float* __restrict__ sa_wk,
             const float* __restrict__ sa_wv, const float* __restrict__ sa_wo,
             const float* __restrict__ ca_wq, const float* __restrict__ ca_wk,
             const float* __restrict__ ca_wv, const float* __restrict__ ca_wo,
             const float* __restrict__ ff_w1, const float* __restrict__ ff_w2,
             const float* __restrict__ enc,
             const float* __restrict__ sa_bq, const float* __restrict__ sa_bk,
             const float* __restrict__ sa_bv,
             const float* __restrict__ ca_bq,
             const float* __restrict__ ca_bk, const float* __restrict__ ca_bv,
             __half* __restrict__ wh, __half* __restrict__ ench,
             float* __restrict__ bqkv, float* __restrict__ bkv,
             float* __restrict__ bqc)
{
    const long i = (long)blockIdx.x*256 + threadIdx.x;
    if (i < 8L*SEGP){
        const int seg = (int)(i / SEGP);
        const int li  = (int)(i % SEGP);
        float4 v = ((const float4*)(seg==0?sa_wq: seg==1?sa_wk: seg==2?sa_wv:
                     seg==3?sa_wo: seg==4?ca_wq: seg==5?ca_wk: seg==6?ca_wv:ca_wo))[li];
        if (seg == 0 || seg == 4){
            v.x *= QSCALE; v.y *= QSCALE; v.z *= QSCALE; v.w *= QSCALE;
        }
        uint2 o; o.x = pack2(v.x, v.y); o.y = pack2(v.z, v.w);
        size_t d;
        const int row = li >> 8, n = (li & 255) * 4;
        if (seg <= 2)       d = (size_t)row*3072 + seg*1024 + n;
        else if (seg == 3)  d = (size_t)3*MEGA + (size_t)li*4;
        else if (seg == 4)  d = (size_t)4*MEGA + (size_t)li*4;
        else if (seg <= 6)  d = (size_t)5*MEGA + (size_t)row*2048 + (seg-5)*1024 + n;
        else                d = (size_t)7*MEGA + (size_t)li*4;
        *(uint2*)&wh[d] = o;
        return;
    }
    long j = i - 8L*SEGP;
    if (j < (long)MEGA){
        const float4 v = ((const float4*)ff_w1)[j];
        uint2 o; o.x = pack2(v.x,v.y); o.y = pack2(v.z,v.w);
        *(uint2*)&wh[(size_t)8*MEGA + (size_t)j*4] = o;
        return;
    }
    j -= MEGA;
    if (j < (long)MEGA){
        const float4 v = ((const float4*)ff_w2)[j];
        uint2 o; o.x = pack2(v.x,v.y); o.y = pack2(v.z,v.w);
        *(uint2*)&wh[(size_t)12*MEGA + (size_t)j*4] = o;
        return;
    }
    j -= MEGA;
    if (j < (long)MEGA){
        const float4 v = ((const float4*)enc)[j];
        uint2 o; o.x = pack2(v.x,v.y); o.y = pack2(v.z,v.w);
        *(uint2*)&ench[(size_t)j*4] = o;
        return;
    }
    j -= MEGA;
    if (j < 768){
        const int e = (int)j * 4;
        const int sub = e >> 10, idx = e & 1023;
        float4 v = *(const float4*)&((sub==0?sa_bq: sub==1?sa_bk:sa_bv)[idx]);
        if (sub == 0){ v.x*=QSCALE; v.y*=QSCALE; v.z*=QSCALE; v.w*=QSCALE; }
        *(float4*)&bqkv[e] = v;
        return;
    }
    j -= 768;
    if (j < 512){
        const int e = (int)j * 4;
        const int sub = e >> 10, idx = e & 1023;
        *(float4*)&bkv[e] = *(const float4*)&((sub==0?ca_bk:ca_bv)[idx]);
        return;
    }
    j -= 512;
    if (j < 256){
        const int e = (int)j * 4;
        float4 v = *(const float4*)&ca_bq[e];
        v.x*=QSCALE; v.y*=QSCALE; v.z*=QSCALE; v.w*=QSCALE;
        *(float4*)&bqc[e] = v;
    }
}

// ---------------- LayerNorm (fp32 in, half out) ----------------
__global__ __launch_bounds__(256)
void ln_kernel(const float* __restrict__ x, const float* __restrict__ gamma,
               const float* __restrict__ beta, __half* __restrict__ out)
{
    const int row = blockIdx.x;
    const int t = threadIdx.x;
    const float4 v = ((const float4*)(x + (size_t)row*EDIM))[t];
    float s  = v.x + v.y + v.z + v.w;
    float ss = v.x*v.x + v.y*v.y + v.z*v.z + v.w*v.w;
#pragma unroll
    for (int o = 16; o; o >>= 1){
        s  += __shfl_xor_sync(0xffffffffu, s,  o);
        ss += __shfl_xor_sync(0xffffffffu, ss, o);
    }
    __shared__ float sh_s[8], sh_ss[8];
    const int w = t >> 5, l = t & 31;
    if (l == 0){ sh_s[w] = s; sh_ss[w] = ss; }
    __syncthreads();
    if (w == 0){
        s  = (l < 8) ? sh_s[l]  : 0.f;
        ss = (l < 8) ? sh_ss[l] : 0.f;
#pragma unroll
        for (int o = 4; o; o >>= 1){
            s  += __shfl_xor_sync(0xffffffffu, s,  o);
            ss += __shfl_xor_sync(0xffffffffu, ss, o);
        }
        if (l == 0){ sh_s[0] = s; sh_ss[0] = ss; }
    }
    __syncthreads();
    const float mu   = sh_s[0] * (1.f/EDIM);
    const float var  = sh_ss[0] * (1.f/EDIM) - mu*mu;
    const float rstd = rsqrtf(var + LN_EPS);
    const float4 g4 = ((const float4*)gamma)[t];
    const float4 b4 = ((const float4*)beta)[t];
    __half2* orow = (__half2*)(out + (size_t)row*EDIM);
    orow[2*t]   = __floats2half2_rn((v.x-mu)*rstd*g4.x + b4.x, (v.y-mu)*rstd*g4.y + b4.y);
    orow[2*t+1] = __floats2half2_rn((v.z-mu)*rstd*g4.z + b4.z, (v.w-mu)*rstd*g4.w + b4.w);
}

// ---------------- FP16 GEMM, BK=64, 3-stage cp.async + ldmatrix (R13) --------
#define ASTG 9216
#define BSTG 8704
#define GEMM_SMEM ((3*(ASTG + BSTG))*2)
template<bool RELU, bool RES, bool OUTH>
__global__ __launch_bounds__(256,2)
void gemm_h(const __half* __restrict__ A, const __half* __restrict__ W,
            const float* __restrict__ bias, const float* __restrict__ res,
            void* __restrict__ Cv, int N, int K)
{
    extern __shared__ __half gsm[];
    __half* As = gsm;
    __half* Bs = gsm + 3*ASTG;

    const int tid  = threadIdx.x;
    const int lane = tid & 31;
    const int wid  = tid >> 5;
    const int gid  = lane >> 2;
    const int tig  = lane & 3;
    const int wm   = (wid & 3) * 32;
    const int wn   = (wid >> 2) * 64;
    const int m0 = blockIdx.y * 128;
    const int n0 = blockIdx.x * 128;

    const uint32_t asb = (uint32_t)__cvta_generic_to_shared(As);
    const uint32_t bsb = (uint32_t)__cvta_generic_to_shared(Bs);

    const int a_r = wm + (lane&7) + ((lane>>3)&1)*8;
    const int a_k = ((lane>>4)&1)*8;
    const int b_k = (lane&7) + ((lane>>3)&1)*8;
    const int b_n = wn + ((lane>>4)&1)*8;

    float acc[2][8][4];
#pragma unroll
    for (int i=0;i<2;i++)
#pragma unroll
        for (int j=0;j<8;j++)
#pragma unroll
            for (int k=0;k<4;k++) acc[i][j][k]=0.f;

#define LOADSTAGE(b_, kt_) do{                                               \
        _Pragma("unroll")                                                    \
        for (int i=0;i<4;i++){                                               \
            int idx = tid + 256*i;                                           \
            int ar = idx>>3, ac = (idx&7)*8;                                 \
            cpa16(asb + (uint32_t)(((b_)*ASTG + ar*72 + ac)*2),              \
                  A + (size_t)(m0+ar)*K + (kt_)*64 + ac);                    \
        }                                                                    \
        _Pragma("unroll")                                                    \
        for (int i=0;i<4;i++){                                               \
            int idx = tid + 256*i;                                           \
            int kr = idx>>4, nc = (idx&15)*8;                                \
            cpa16(bsb + (uint32_t)(((b_)*BSTG + kr*136 + nc)*2),             \
                  W + (size_t)((kt_)*64+kr)*N + n0 + nc);                    \
        }                                                                    \
        CP_COMMIT();                                                         \
    }while(0)

    LOADSTAGE(0, 0);
    LOADSTAGE(1, 1);
    const int KT = K >> 6;
    for (int kt = 0; kt < KT; ++kt){
        CP_WAIT(1);
        __syncthreads();
        if (kt + 2 < KT) LOADSTAGE((kt+2)%3, kt+2);
        else CP_COMMIT();
        const int buf = kt % 3;
        const uint32_t asb_b = asb + (uint32_t)(buf*ASTG*2);
        const uint32_t bsb_b = bsb + (uint32_t)(buf*BSTG*2);
#pragma unroll
        for (int kc = 0; kc < 4; kc++){
            uint32_t af[2][4];
#pragma unroll
            for (int ma = 0; ma < 2; ma++)
                ldsm4(af[ma], asb_b + (uint32_t)(((a_r + ma*16)*72 + a_k + kc*16)*2));
#pragma unroll
            for (int np = 0; np < 4; np++){
                uint32_t bf[4];
                ldsm4t(bf, bsb_b + (uint32_t)(((b_k + kc*16)*136 + b_n + np*16)*2));
                mma_f16(acc[0][2*np  ], af[0], bf[0], bf[1]);
                mma_f16(acc[0][2*np+1], af[0], bf[2], bf[3]);
                mma_f16(acc[1][2*np  ], af[1], bf[0], bf[1]);
                mma_f16(acc[1][2*np+1], af[1], bf[2], bf[3]);
            }
        }
    }
#undef LOADSTAGE

#pragma unroll
    for (int ma = 0; ma < 2; ma++){
        const int r0 = m0 + wm + ma*16 + gid;
        const int r1 = r0 + 8;
#pragma unroll
        for (int na = 0; na < 8; na++){
            const int c = n0 + wn + na*8 + 2*tig;
            const float2 bb = *(const float2*)&bias[c];
            float v00 = acc[ma][na][0] + bb.x;
            float v01 = acc[ma][na][1] + bb.y;
            float v10 = acc[ma][na][2] + bb.x;
            float v11 = acc[ma][na][3] + bb.y;
            if (RELU){
                v00 = fmaxf(v00,0.f); v01 = fmaxf(v01,0.f);
                v10 = fmaxf(v10,0.f); v11 = fmaxf(v11,0.f);
            }
            if (RES){
                const float2 q0 = *(const float2*)&res[(size_t)r0*N + c];
                const float2 q1 = *(const float2*)&res[(size_t)r1*N + c];
                v00 += q0.x; v01 += q0.y; v10 += q1.x; v11 += q1.y;
            }
            if (OUTH){
                __half* Ch = (__half*)Cv;
                *(__half2*)&Ch[(size_t)r0*N + c] = __floats2half2_rn(v00, v01);
                *(__half2*)&Ch[(size_t)r1*N + c] = __floats2half2_rn(v10, v11);
            } else {
                float* Cf = (float*)Cv;
                float2 o0; o0.x=v00; o0.y=v01;
                float2 o1; o1.x=v10; o1.y=v11;
                *(float2*)&Cf[(size_t)r0*N + c] = o0;
                *(float2*)&Cf[(size_t)r1*N + c] = o1;
            }
        }
    }
}

// ---------------- Flash attention fp16 (R13 proven loop) ----------------
#define ATP 72
#define KVB (64*ATP)
#define ATTN_SMEM ((128*ATP + 4*KVB)*2)
template<bool CAUSAL>
__global__ __launch_bounds__(256,2)
void attn_h(const __half* __restrict__ Qg, const __half* __restrict__ Kg,
            const __half* __restrict__ Vg, __half* __restrict__ Og,
            int ldq, int ldkv)
{
    extern __shared__ __half smh[];
    __half* Qs = smh;
    __half* Ks = Qs + 128*ATP;
    __half* Vs = Ks + 2*KVB;

    const int tid  = threadIdx.x;
    const int lane = tid & 31;
    const int wid  = tid >> 5;
    const int gid  = lane >> 2;
    const int tig  = lane & 3;
    const int wm   = wid * 16;
    const int qb = CAUSAL ? ((int)gridDim.x - 1 - (int)blockIdx.x) : (int)blockIdx.x;
    const int h = blockIdx.y, b = blockIdx.z;
    const size_t baseq = (size_t)b*TSEQ*ldq  + (size_t)h*64;
    const size_t basek = (size_t)b*TSEQ*ldkv + (size_t)h*64;
    const size_t baseo = (size_t)b*TSEQ*EDIM + (size_t)h*64;

    const uint32_t qsb = (uint32_t)__cvta_generic_to_shared(Qs);
    const uint32_t ksb = (uint32_t)__cvta_generic_to_shared(Ks);
    const uint32_t vsb = (uint32_t)__cvta_generic_to_shared(Vs);

#pragma unroll
    for (int i = 0; i < 4; i++){
        int idx = tid + 256*i;
        int r = idx>>3, c = (idx&7)*8;
        cpa16(qsb + (uint32_t)((r*ATP + c)*2), Qg + baseq + (size_t)(qb*128 + r)*ldq + c);
    }
    CP_COMMIT();
#define LOADKV(b_, kt_) do{                                                   \
        _Pragma("unroll")                                                     \
        for (int i = 0; i < 2; i++){                                          \
            int idx = tid + 256*i;                                            \
            int r = idx>>3, c = (idx&7)*8;                                    \
            size_t go = basek + (size_t)((kt_)*64 + r)*ldkv + c;              \
            uint32_t so = (uint32_t)(((b_)*KVB + r*ATP + c)*2);               \
            cpa16(ksb + so, Kg + go);                                         \
            cpa16(vsb + so, Vg + go);                                         \
        }                                                                     \
        CP_COMMIT();                                                          \
    }while(0)
    LOADKV(0, 0);
    CP_WAIT(1);
    __syncthreads();

    const int q_r = wm + (lane&7) + ((lane>>3)&1)*8;
    const int q_k = ((lane>>4)&1)*8;
    uint32_t qf[4][4];
#pragma unroll
    for (int kc = 0; kc < 4; kc++)
        ldsm4(qf[kc], qsb + (uint32_t)((q_r*ATP + q_k + kc*16)*2));

    const int k_r = (lane&7);
    const int k_c = (lane>>3)*8;
    const int v_r = (lane&7) + ((lane>>3)&1)*8;
    const int v_n = ((lane>>4)&1)*8;

    float oacc[8][4];
#pragma unroll
    for (int i=0;i<8;i++)
#pragma unroll
        for (int j=0;j<4;j++) oacc[i][j]=0.f;
    float m0=-1e30f, m1=-1e30f, l0=0.f, l1=0.f;

    const int nkt = CAUSAL ? (2*qb + 2) : (TSEQ/64);
    const int gr0 = qb*128 + wm + gid;
    const int gr1 = gr0 + 8;

    for (int kt = 0; kt < nkt; ++kt){
        CP_WAIT(0);
        __syncthreads();
        const int buf = kt & 1;
        if (kt + 1 < nkt) LOADKV(buf^1, kt+1);
        const uint32_t ksb_b = ksb + (uint32_t)(buf*KVB*2);
        const uint32_t vsb_b = vsb + (uint32_t)(buf*KVB*2);

        float sa[8][4];
#pragma unroll
        for (int na=0;na<8;na++)
#pragma unroll
            for (int e=0;e<4;e++) sa[na][e]=0.f;
#pragma unroll
        for (int na = 0; na < 8; na++){
#pragma unroll
            for (int kq = 0; kq < 2; kq++){
                uint32_t kf[4];
                ldsm4(kf, ksb_b + (uint32_t)(((na*8 + k_r)*ATP + kq*32 + k_c)*2));
                mma_f16(sa[na], qf[2*kq  ], kf[0], kf[1]);
                mma_f16(sa[na], qf[2*kq+1], kf[2], kf[3]);
            }
        }
        if (CAUSAL && kt >= 2*qb){
#pragma unroll
            for (int na = 0; na < 8; na++){
                const int c0 = kt*64 + na*8 + 2*tig;
#pragma unroll
                for (int e = 0; e < 4; e++){
                    const int col = c0 + (e&1);
                    const int row = (e<2) ? gr0 : gr1;
                    if (col > row) sa[na][e] = -1e30f;
                }
            }
        }
        float mx0=-1e30f, mx1=-1e30f;
#pragma unroll
        for (int na=0;na<8;na++){
            mx0 = fmaxf(mx0, fmaxf(sa[na][0], sa[na][1]));
            mx1 = fmaxf(mx1, fmaxf(sa[na][2], sa[na][3]));
        }
        mx0 = fmaxf(mx0, __shfl_xor_sync(0xffffffffu, mx0, 1));
        mx0 = fmaxf(mx0, __shfl_xor_sync(0xffffffffu, mx0, 2));
        mx1 = fmaxf(mx1, __shfl_xor_sync(0xffffffffu, mx1, 1));
        mx1 = fmaxf(mx1, __shfl_xor_sync(0xffffffffu, mx1, 2));
        const float mn0 = fmaxf(m0, mx0);
        const float mn1 = fmaxf(m1, mx1);
        const float al0 = exp2f(m0 - mn0);
        const float al1 = exp2f(m1 - mn1);
        m0 = mn0; m1 = mn1;
        uint32_t pf[4][4];
#pragma unroll
        for (int kc = 0; kc < 4; kc++){
            pf[kc][0] = pexp2(sa[2*kc  ][0]-mn0, sa[2*kc  ][1]-mn0);
            pf[kc][1] = pexp2(sa[2*kc  ][2]-mn1, sa[2*kc  ][3]-mn1);
            pf[kc][2] = pexp2(sa[2*kc+1][0]-mn0, sa[2*kc+1][1]-mn0);
            pf[kc][3] = pexp2(sa[2*kc+1][2]-mn1, sa[2*kc+1][3]-mn1);
        }
        float lacc[4] = {0.f, 0.f, 0.f, 0.f};
#pragma unroll
        for (int kc = 0; kc < 4; kc++)
            mma_f16(lacc, pf[kc], HONES, HONES);
        l0 = l0*al0 + lacc[0];
        l1 = l1*al1 + lacc[2];
#pragma unroll
        for (int na=0;na<8;na++){
            oacc[na][0]*=al0; oacc[na][1]*=al0;
            oacc[na][2]*=al1; oacc[na][3]*=al1;
        }
#pragma unroll
        for (int kc = 0; kc < 4; kc++){
#pragma unroll
            for (int np = 0; np < 4; np++){
                uint32_t vf[4];
                ldsm4t(vf, vsb_b + (uint32_t)(((kc*16 + v_r)*ATP + v_n + np*16)*2));
                mma_f16(oacc[2*np  ], pf[kc], vf[0], vf[1]);
                mma_f16(oacc[2*np+1], pf[kc], vf[2], vf[3]);
            }
        }
    }
#undef LOADKV

    const float li0 = 1.f / l0;
    const float li1 = 1.f / l1;
#pragma unroll
    for (int na = 0; na < 8; na++){
        const int c = na*8 + 2*tig;
        *(__half2*)&Og[baseo + (size_t)gr0*EDIM + c] =
            __floats2half2_rn(oacc[na][0]*li0, oacc[na][1]*li0);
        *(__half2*)&Og[baseo + (size_t)gr1*EDIM + c] =
            __floats2half2_rn(oacc[na][2]*li1, oacc[na][3]*li1);
    }
}

// ---------------- launch ----------------
extern "C" void kernel_launch(void* const* d_in, const int* in_sizes, int n_in,
                              void* d_out, int out_size)
{
    const float* x     = (const float*)d_in[0];
    const float* enc   = (const float*)d_in[1];
    const float* sa_wq = (const float*)d_in[3];  const float* sa_bq = (const float*)d_in[4];
    const float* sa_wk = (const float*)d_in[5];  const float* sa_bk = (const float*)d_in[6];
    const float* sa_wv = (const float*)d_in[7];  const float* sa_bv = (const float*)d_in[8];
    const float* sa_wo = (const float*)d_in[9];  const float* sa_bo = (const float*)d_in[10];
    const float* ca_wq = (const float*)d_in[11]; const float* ca_bq = (const float*)d_in[12];
    const float* ca_wk = (const float*)d_in[13]; const float* ca_bk = (const float*)d_in[14];
    const float* ca_wv = (const float*)d_in[15]; const float* ca_bv = (const float*)d_in[16];
    const float* ca_wo = (const float*)d_in[17]; const float* ca_bo = (const float*)d_in[18];
    const float* ff_w1 = (const float*)d_in[19]; const float* ff_b1 = (const float*)d_in[20];
    const float* ff_w2 = (const float*)d_in[21]; const float* ff_b2 = (const float*)d_in[22];
    const float* ln1g  = (const float*)d_in[23]; const float* ln1b  = (const float*)d_in[24];
    const float* ln2g  = (const float*)d_in[25]; const float* ln2b  = (const float*)d_in[26];
    const float* ln3g  = (const float*)d_in[27]; const float* ln3b  = (const float*)d_in[28];
    float* out = (float*)d_out;

    __half *wh, *ench, *hh, *qkvh, *kvc, *qh, *aoh, *ffh;
    float *x1, *x2, *bqkv, *bkv, *bqc;
    cudaGetSymbolAddress((void**)&wh,   g_wh);
    cudaGetSymbolAddress((void**)&ench, g_ench);
    cudaGetSymbolAddress((void**)&hh,   g_hh);
    cudaGetSymbolAddress((void**)&qkvh, g_qkvh);
    cudaGetSymbolAddress((void**)&kvc,  g_kvc);
    cudaGetSymbolAddress((void**)&qh,   g_qh);
    cudaGetSymbolAddress((void**)&aoh,  g_aoh);
    cudaGetSymbolAddress((void**)&ffh,  g_ffh);
    cudaGetSymbolAddress((void**)&x1,   g_x1);
    cudaGetSymbolAddress((void**)&x2,   g_x2);
    cudaGetSymbolAddress((void**)&bqkv, g_bqkv);
    cudaGetSymbolAddress((void**)&bkv,  g_bkv);
    cudaGetSymbolAddress((void**)&bqc,  g_bqc);

    cudaFuncSetAttribute(attn_h<true>,  cudaFuncAttributeMaxDynamicSharedMemorySize, ATTN_SMEM);
    cudaFuncSetAttribute(attn_h<false>, cudaFuncAttributeMaxDynamicSharedMemorySize, ATTN_SMEM);
    cudaFuncSetAttribute(gemm_h<false,false,true >, cudaFuncAttributeMaxDynamicSharedMemorySize, GEMM_SMEM);
    cudaFuncSetAttribute(gemm_h<false,true ,false>, cudaFuncAttributeMaxDynamicSharedMemorySize, GEMM_SMEM);
    cudaFuncSetAttribute(gemm_h<true ,false,true >, cudaFuncAttributeMaxDynamicSharedMemorySize, GEMM_SMEM);

    // side stream + events (created once; host-side only, no device alloc)
    static cudaStream_t s1 = nullptr;
    static cudaEvent_t evCvt = nullptr, evKV = nullptr;
    if (!s1){
        cudaStreamCreateWithFlags(&s1, cudaStreamNonBlocking);
        cudaEventCreateWithFlags(&evCvt, cudaEventDisableTiming);
        cudaEventCreateWithFlags(&evKV,  cudaEventDisableTiming);
    }

    const long cvt_total = 8L*SEGP + 3L*MEGA + 1536;
    cvt_all<<<(unsigned)((cvt_total + 255)/256), 256>>>(
        sa_wq, sa_wk, sa_wv, sa_wo, ca_wq, ca_wk, ca_wv, ca_wo,
        ff_w1, ff_w2, enc, sa_bq, sa_bk, sa_bv, ca_bq, ca_bk, ca_bv,
        wh, ench, bqkv, bkv, bqc);
    cudaEventRecord(evCvt, 0);

    const dim3 thr(256);
    const dim3 gQKV(3072/128, NTOK/128);
    const dim3 gKV (2048/128, NTOK/128);
    const dim3 gP  (EDIM/128, NTOK/128);
    const dim3 gF1 (FFD/128,  NTOK/128);
    const dim3 gA  (TSEQ/128, 16, 2);

    // side stream: cross-attention KV projection (depends only on enc)
    cudaStreamWaitEvent(s1, evCvt, 0);
    gemm_h<false,false,true ><<<gKV, thr, GEMM_SMEM, s1>>>(ench, wh+(size_t)5*MEGA, bkv, nullptr, kvc, 2048, 1024);
    cudaEventRecord(evKV, s1);

    // ---- self attention ----
    ln_kernel<<<NTOK, 256>>>(x, ln1g, ln1b, hh);
    gemm_h<false,false,true ><<<gQKV, thr, GEMM_SMEM>>>(hh, wh, bqkv, nullptr, qkvh, 3072, 1024);
    attn_h<true><<<gA, thr, ATTN_SMEM>>>(qkvh, qkvh+1024, qkvh+2048, aoh, 3072, 3072);
    gemm_h<false,true ,false><<<gP, thr, GEMM_SMEM>>>(aoh, wh+(size_t)3*MEGA, sa_bo, x, x1, EDIM, EDIM);

    // ---- cross attention ----
    ln_kernel<<<NTOK, 256>>>(x1, ln2g, ln2b, hh);
    gemm_h<false,false,true ><<<gP, thr, GEMM_SMEM>>>(hh, wh+(size_t)4*MEGA, bqc, nullptr, qh, EDIM, 1024);
    cudaStreamWaitEvent(0, evKV, 0);     // rejoin side stream before reading kvc
    attn_h<false><<<gA, thr, ATTN_SMEM>>>(qh, kvc, kvc+1024, aoh, 1024, 2048);
    gemm_h<false,true ,false><<<gP, thr, GEMM_SMEM>>>(aoh, wh+(size_t)7*MEGA, ca_bo, x1, x2, EDIM, EDIM);

    // ---- feed-forward ----
    ln_kernel<<<NTOK, 256>>>(x2, ln3g, ln3b, hh);
    gemm_h<true ,false,true ><<<gF1, thr, GEMM_SMEM>>>(hh,  wh+(size_t)8*MEGA,  ff_b1, nullptr, ffh, FFD, 1024);
    gemm_h<false,true ,false><<<gP, thr, GEMM_SMEM>>>(ffh, wh+(size_t)12*MEGA, ff_b2, x2, out, EDIM, FFD);
}